// round 2
// baseline (speedup 1.0000x reference)
#include <cuda_runtime.h>
#include <cstdint>

// Problem constants
#define EXPERTS 8
#define HID     2048
#define INTER   4096
#define TWO_I   8192
#define TOK     1024
#define TOPK    2
#define NPAIR   2048   // TOK * TOPK
#define GSIZE   128

// ---------------------------------------------------------------------------
// Scratch (static __device__ globals — no allocation allowed)
// ---------------------------------------------------------------------------
__device__ float g_gu[(size_t)NPAIR * TWO_I];   // gate|up pre-activation
__device__ float g_h [(size_t)NPAIR * INTER];   // gelu(gate)*up
__device__ float g_dn[(size_t)NPAIR * HID];     // coef * (h @ dn^T)
__device__ int   g_cnt[EXPERTS];
__device__ int   g_list[EXPERTS][NPAIR];
__device__ float g_coef[NPAIR];

// input-marshaling flags (set by k_detect each launch; deterministic)
__device__ int g_wmode;    // 0 = packed uint8 bytes, 1 = widened to int32 (1 byte/word)
__device__ int g_swap_gu;  // 1 = (a,b) is (zeros,scales) for gate_up pair
__device__ int g_swap_dn;  // same for down pair
__device__ int g_swap_rt;  // 1 = (a,b) is (weights,indices) for routing pair

// ---------------------------------------------------------------------------
// Input introspection (device-side; cheap, single warp)
// ---------------------------------------------------------------------------
__global__ void k_detect(const uint32_t* __restrict__ gup,
                         const float* __restrict__ gus_a,
                         const float* __restrict__ dns_a,
                         const uint32_t* __restrict__ rt_a)
{
    if (threadIdx.x != 0) return;
    // (i) packed-weight storage: raw uint8 stream vs int32-widened bytes
    int widened = 1;
    for (int i = 0; i < 16; i++)
        if (gup[i] & 0xFFFFFF00u) widened = 0;
    g_wmode = widened;
    // (ii) scales (positive) vs zeros (negative) — sign vote
    int neg = 0;
    for (int i = 0; i < 9; i++) neg += (gus_a[i] < 0.f) ? 1 : 0;
    g_swap_gu = (neg > 4) ? 1 : 0;
    neg = 0;
    for (int i = 0; i < 9; i++) neg += (dns_a[i] < 0.f) ? 1 : 0;
    g_swap_dn = (neg > 4) ? 1 : 0;
    // (iii) router indices (u32 values 0..7) vs routing weights (float bits, large)
    int small = 1;
    for (int i = 0; i < 16; i++)
        if (rt_a[i] >= 256u) small = 0;
    g_swap_rt = small ? 0 : 1;
}

// ---------------------------------------------------------------------------
// Routing
// ---------------------------------------------------------------------------
__global__ void k_zero() {
    if (threadIdx.x < EXPERTS) g_cnt[threadIdx.x] = 0;
}

__global__ void k_route(const void* __restrict__ a, const void* __restrict__ b) {
    const int*   ridx = (const int*)  (g_swap_rt ? b : a);
    const float* rw   = (const float*)(g_swap_rt ? a : b);
    int i = blockIdx.x * blockDim.x + threadIdx.x;
    if (i >= NPAIR) return;
    int e = ridx[i];
    int pos = atomicAdd(&g_cnt[e], 1);
    g_list[e][pos] = i;
    g_coef[i] = rw[i];
}

// ---------------------------------------------------------------------------
// Dequantized GEMM:  C[pid][r] = (coef?) * sum_h A[arow][h] * W_e[r][h]
//   PHASE 0 (gate_up): A = x (arow = pid>>1), RTOT=2I, INF=H,  C=g_gu
//   PHASE 1 (down)   : A = g_h (arow = pid), RTOT=H,  INF=I,  C=g_dn, *coef
// ---------------------------------------------------------------------------
template <int PHASE>
__global__ void __launch_bounds__(256)
dq_gemm(const float* __restrict__ xin,
        const uint8_t* __restrict__ wpk,
        const float* __restrict__ pa,    // scales-or-zeros candidate A
        const float* __restrict__ pb)    // scales-or-zeros candidate B
{
    constexpr int RTOT  = PHASE ? HID   : TWO_I;
    constexpr int INF   = PHASE ? INTER : HID;
    constexpr int SHIFT = PHASE ? 0 : 1;
    constexpr int NGRP  = INF / GSIZE;
    constexpr int INFH  = INF / 2;

    const int e  = blockIdx.y;
    const int n  = g_cnt[e];
    const int t0 = blockIdx.z * 64;
    if (t0 >= n) return;
    const int r0  = blockIdx.x * 64;
    const int tid = threadIdx.x;

    const int swp = PHASE ? g_swap_dn : g_swap_gu;
    const float* __restrict__ sc = swp ? pb : pa;
    const float* __restrict__ zp = swp ? pa : pb;
    const int wmode = g_wmode;

    __shared__ float Xs[64][65];
    __shared__ float Ws[64][65];
    __shared__ int   s_pid[64];

    const float* A = PHASE ? g_h : xin;
    float*       C = PHASE ? g_dn : g_gu;

    if (tid < 64) {
        int slot = t0 + tid;
        s_pid[tid] = (slot < n) ? g_list[e][slot] : -1;
    }
    __syncthreads();

    float acc[4][4];
    #pragma unroll
    for (int i = 0; i < 4; i++)
        #pragma unroll
        for (int j = 0; j < 4; j++) acc[i][j] = 0.f;

    const int tcol4 = (tid & 15) * 4;   // this thread's 4 tokens
    const int rrow4 = (tid >> 4) * 4;   // this thread's 4 rows

    const size_t wrowbase = (size_t)e * RTOT + r0;

    for (int h0 = 0; h0 < INF; h0 += 64) {
        __syncthreads();   // previous chunk fully consumed

        // ---- load activations: 64 tokens x 64 cols, float4 global loads ----
        #pragma unroll
        for (int i = 0; i < 4; i++) {
            int idx  = tid + i * 256;
            int trow = idx >> 4;
            int c4   = (idx & 15) * 4;
            int p    = s_pid[trow];
            float4 v = make_float4(0.f, 0.f, 0.f, 0.f);
            if (p >= 0) {
                const float* src = A + (size_t)(p >> SHIFT) * INF + h0 + c4;
                v = *reinterpret_cast<const float4*>(src);
            }
            Xs[trow][c4 + 0] = v.x;
            Xs[trow][c4 + 1] = v.y;
            Xs[trow][c4 + 2] = v.z;
            Xs[trow][c4 + 3] = v.w;
        }

        // ---- load + dequant weights: 64 rows x 64 cols (32 packed bytes/row)
        const int gidx = h0 >> 7;
        #pragma unroll
        for (int i = 0; i < 2; i++) {
            int ui = tid + i * 256;            // 0..511
            int r  = ui >> 3;                  // 0..63
            int b  = ui & 7;                   // 4-byte unit within chunk row
            size_t row  = wrowbase + r;
            size_t eoff = row * INFH + (h0 >> 1) + b * 4;  // packed-byte index
            uint32_t bytes4;
            if (wmode == 0) {
                bytes4 = *reinterpret_cast<const uint32_t*>(wpk + eoff);
            } else {
                // widened: one original byte per 32-bit word
                const uint4 v4 = *reinterpret_cast<const uint4*>(
                    reinterpret_cast<const uint32_t*>(wpk) + eoff);
                bytes4 = (v4.x & 0xFFu) | ((v4.y & 0xFFu) << 8)
                       | ((v4.z & 0xFFu) << 16) | ((v4.w & 0xFFu) << 24);
            }
            float s = sc[row * NGRP + gidx];
            float z = zp[row * NGRP + gidx];
            #pragma unroll
            for (int kk = 0; kk < 4; kk++) {
                uint32_t byte = (bytes4 >> (8 * kk)) & 0xFFu;
                int col = b * 8 + kk * 2;
                Ws[r][col + 0] = (float)(byte >> 4)  * s + z;  // high -> even
                Ws[r][col + 1] = (float)(byte & 15u) * s + z;  // low  -> odd
            }
        }
        __syncthreads();

        // ---- 4x4 register-tiled FMA over the 64-wide chunk ----
        #pragma unroll
        for (int h = 0; h < 64; h++) {
            float xv[4], wv[4];
            #pragma unroll
            for (int i = 0; i < 4; i++) xv[i] = Xs[tcol4 + i][h];
            #pragma unroll
            for (int j = 0; j < 4; j++) wv[j] = Ws[rrow4 + j][h];
            #pragma unroll
            for (int i = 0; i < 4; i++)
                #pragma unroll
                for (int j = 0; j < 4; j++)
                    acc[i][j] += xv[i] * wv[j];
        }
    }

    // ---- store ----
    #pragma unroll
    for (int i = 0; i < 4; i++) {
        int p = s_pid[tcol4 + i];
        if (p < 0) continue;
        float cf = PHASE ? g_coef[p] : 1.f;
        float* dst = C + (size_t)p * RTOT + r0 + rrow4;
        #pragma unroll
        for (int j = 0; j < 4; j++) dst[j] = acc[i][j] * cf;
    }
}

// ---------------------------------------------------------------------------
// gelu(gate) * up   (tanh approximation)
// ---------------------------------------------------------------------------
__global__ void k_gelu() {
    int i = blockIdx.x * blockDim.x + threadIdx.x;
    if (i >= NPAIR * INTER) return;
    int pid = i >> 12;
    int j   = i & (INTER - 1);
    float g = g_gu[(size_t)pid * TWO_I + j];
    float u = g_gu[(size_t)pid * TWO_I + INTER + j];
    float t = tanhf(0.7978845608028654f * (g + 0.044715f * g * g * g));
    g_h[i] = 0.5f * g * (1.f + t) * u;
}

// ---------------------------------------------------------------------------
// combine: out[t][c] = down(pair 2t) + down(pair 2t+1)
// ---------------------------------------------------------------------------
__global__ void k_comb(float* __restrict__ out) {
    int i = blockIdx.x * blockDim.x + threadIdx.x;
    if (i >= TOK * HID) return;
    int t = i >> 11;
    int c = i & (HID - 1);
    out[i] = g_dn[(size_t)(2 * t) * HID + c] + g_dn[(size_t)(2 * t + 1) * HID + c];
}

// ---------------------------------------------------------------------------
extern "C" void kernel_launch(void* const* d_in, const int* in_sizes, int n_in,
                              void* d_out, int out_size)
{
    (void)out_size;
    // Default positional mapping (setup_inputs dict order)
    int ix = 0, igup = 1, igs_a = 2, igs_b = 3, idnp = 4, ids_a = 5, ids_b = 6,
        irt_a = 7, irt_b = 8;

    // Robust mapping by element counts (unique per tensor / pair)
    int gu_pair[2] = {-1, -1}, dn_pair[2] = {-1, -1}, rt_pair[2] = {-1, -1};
    int f_x = -1, f_gup = -1, f_dnp = -1;
    for (int i = 0; i < n_in; i++) {
        long long s = in_sizes[i];
        if      (s == 2097152LL)  f_x = i;
        else if (s == 67108864LL) f_gup = i;
        else if (s == 33554432LL) f_dnp = i;
        else if (s == 1048576LL)  { if (gu_pair[0] < 0) gu_pair[0] = i; else gu_pair[1] = i; }
        else if (s == 524288LL)   { if (dn_pair[0] < 0) dn_pair[0] = i; else dn_pair[1] = i; }
        else if (s == 2048LL)     { if (rt_pair[0] < 0) rt_pair[0] = i; else rt_pair[1] = i; }
    }
    if (f_x >= 0 && f_gup >= 0 && f_dnp >= 0 &&
        gu_pair[1] >= 0 && dn_pair[1] >= 0 && rt_pair[1] >= 0) {
        ix = f_x; igup = f_gup; idnp = f_dnp;
        igs_a = gu_pair[0]; igs_b = gu_pair[1];
        ids_a = dn_pair[0]; ids_b = dn_pair[1];
        irt_a = rt_pair[0]; irt_b = rt_pair[1];
    }

    const float*   x    = (const float*)  d_in[ix];
    const uint8_t* gu_p = (const uint8_t*)d_in[igup];
    const float*   gu_a = (const float*)  d_in[igs_a];
    const float*   gu_b = (const float*)  d_in[igs_b];
    const uint8_t* dn_p = (const uint8_t*)d_in[idnp];
    const float*   dn_a = (const float*)  d_in[ids_a];
    const float*   dn_b = (const float*)  d_in[ids_b];
    const void*    rt_a = d_in[irt_a];
    const void*    rt_b = d_in[irt_b];
    float*         out  = (float*)        d_out;

    k_detect<<<1, 32>>>((const uint32_t*)gu_p, gu_a, dn_a, (const uint32_t*)rt_a);
    k_zero<<<1, 32>>>();
    k_route<<<NPAIR / 256, 256>>>(rt_a, rt_b);

    dim3 g0(TWO_I / 64, EXPERTS, NPAIR / 64);
    dq_gemm<0><<<g0, 256>>>(x, gu_p, gu_a, gu_b);

    k_gelu<<<(NPAIR * INTER) / 256, 256>>>();

    dim3 g1(HID / 64, EXPERTS, NPAIR / 64);
    dq_gemm<1><<<g1, 256>>>(x, dn_p, dn_a, dn_b);

    k_comb<<<(TOK * HID) / 256, 256>>>(out);
}

// round 3
// speedup vs baseline: 2.9189x; 2.9189x over previous
#include <cuda_runtime.h>
#include <cuda_bf16.h>
#include <cstdint>

#define EXPERTS 8
#define HID     2048
#define INTER   4096
#define TWO_I   8192
#define TOK     1024
#define NPAIR   2048
#define GSIZE   128

// ---------------------------------------------------------------------------
// Scratch (static __device__ globals)
// ---------------------------------------------------------------------------
__device__ float         g_gu [(size_t)NPAIR * TWO_I];   // gate|up pre-activation (fp32)
__device__ __nv_bfloat16 g_hhi[(size_t)NPAIR * INTER];   // h hi
__device__ __nv_bfloat16 g_hlo[(size_t)NPAIR * INTER];   // h lo
__device__ __nv_bfloat16 g_xhi[(size_t)TOK * HID];
__device__ __nv_bfloat16 g_xlo[(size_t)TOK * HID];
__device__ float         g_S0[TOK][HID / GSIZE];         // 16 group sums of x
__device__ float         g_S1[NPAIR][INTER / GSIZE];     // 32 group sums of h
__device__ float         g_dn[(size_t)NPAIR * HID];
__device__ int   g_cnt[EXPERTS];
__device__ int   g_list[EXPERTS][NPAIR];
__device__ float g_coef[NPAIR];

// input-marshaling flags (set by k_detect each launch; deterministic)
__device__ int g_wmode, g_swap_gu, g_swap_dn, g_swap_rt;

// ---------------------------------------------------------------------------
__global__ void k_detect(const uint32_t* __restrict__ gup,
                         const float* __restrict__ gus_a,
                         const float* __restrict__ dns_a,
                         const uint32_t* __restrict__ rt_a)
{
    if (threadIdx.x != 0) return;
    int widened = 1;
    for (int i = 0; i < 16; i++)
        if (gup[i] & 0xFFFFFF00u) widened = 0;
    g_wmode = widened;
    int neg = 0;
    for (int i = 0; i < 9; i++) neg += (gus_a[i] < 0.f) ? 1 : 0;
    g_swap_gu = (neg > 4) ? 1 : 0;
    neg = 0;
    for (int i = 0; i < 9; i++) neg += (dns_a[i] < 0.f) ? 1 : 0;
    g_swap_dn = (neg > 4) ? 1 : 0;
    int small = 1;
    for (int i = 0; i < 16; i++)
        if (rt_a[i] >= 256u) small = 0;
    g_swap_rt = small ? 0 : 1;
}

__global__ void k_zero() {
    if (threadIdx.x < EXPERTS) g_cnt[threadIdx.x] = 0;
}

__global__ void k_route(const void* __restrict__ a, const void* __restrict__ b) {
    const int*   ridx = (const int*)  (g_swap_rt ? b : a);
    const float* rw   = (const float*)(g_swap_rt ? a : b);
    int i = blockIdx.x * blockDim.x + threadIdx.x;
    if (i >= NPAIR) return;
    int e = ridx[i];
    int pos = atomicAdd(&g_cnt[e], 1);
    g_list[e][pos] = i;
    g_coef[i] = rw[i];
}

// ---------------------------------------------------------------------------
// x -> (xhi, xlo) bf16 split + per-group sums S0. One warp per (token, group).
// ---------------------------------------------------------------------------
__global__ void k_split(const float* __restrict__ x) {
    int wg   = blockIdx.x * 8 + (threadIdx.x >> 5);
    int lane = threadIdx.x & 31;
    int token = wg >> 4;            // HID/GSIZE = 16 groups
    int g     = wg & 15;
    size_t base = (size_t)token * HID + g * GSIZE + lane * 4;
    float4 v = *(const float4*)(x + base);
    __nv_bfloat16 h0 = __float2bfloat16(v.x), h1 = __float2bfloat16(v.y);
    __nv_bfloat16 h2 = __float2bfloat16(v.z), h3 = __float2bfloat16(v.w);
    __nv_bfloat16 l0 = __float2bfloat16(v.x - __bfloat162float(h0));
    __nv_bfloat16 l1 = __float2bfloat16(v.y - __bfloat162float(h1));
    __nv_bfloat16 l2 = __float2bfloat16(v.z - __bfloat162float(h2));
    __nv_bfloat16 l3 = __float2bfloat16(v.w - __bfloat162float(h3));
    ((__nv_bfloat162*)(g_xhi + base))[0] = __nv_bfloat162(h0, h1);
    ((__nv_bfloat162*)(g_xhi + base))[1] = __nv_bfloat162(h2, h3);
    ((__nv_bfloat162*)(g_xlo + base))[0] = __nv_bfloat162(l0, l1);
    ((__nv_bfloat162*)(g_xlo + base))[1] = __nv_bfloat162(l2, l3);
    float sum = v.x + v.y + v.z + v.w;
    #pragma unroll
    for (int o = 16; o; o >>= 1) sum += __shfl_xor_sync(0xFFFFFFFFu, sum, o);
    if (lane == 0) g_S0[token][g] = sum;
}

// ---------------------------------------------------------------------------
// gelu(gate)*up in fp32, output split to bf16 hi/lo + group sums S1.
// One warp per (pid, group of 128 in INTER).
// ---------------------------------------------------------------------------
__global__ void k_gelu() {
    int wg   = blockIdx.x * 8 + (threadIdx.x >> 5);
    int lane = threadIdx.x & 31;
    int pid = wg >> 5;              // INTER/GSIZE = 32 groups
    int g   = wg & 31;
    size_t base = (size_t)pid * INTER + g * GSIZE + lane * 4;
    size_t gub  = (size_t)pid * TWO_I + g * GSIZE + lane * 4;
    float4 gg = *(const float4*)(g_gu + gub);
    float4 uu = *(const float4*)(g_gu + gub + INTER);
    float h[4];
    float gv[4] = {gg.x, gg.y, gg.z, gg.w};
    float uv[4] = {uu.x, uu.y, uu.z, uu.w};
    #pragma unroll
    for (int i = 0; i < 4; i++) {
        float t = tanhf(0.7978845608028654f * (gv[i] + 0.044715f * gv[i] * gv[i] * gv[i]));
        h[i] = 0.5f * gv[i] * (1.f + t) * uv[i];
    }
    __nv_bfloat16 hi[4], lo[4];
    #pragma unroll
    for (int i = 0; i < 4; i++) {
        hi[i] = __float2bfloat16(h[i]);
        lo[i] = __float2bfloat16(h[i] - __bfloat162float(hi[i]));
    }
    ((__nv_bfloat162*)(g_hhi + base))[0] = __nv_bfloat162(hi[0], hi[1]);
    ((__nv_bfloat162*)(g_hhi + base))[1] = __nv_bfloat162(hi[2], hi[3]);
    ((__nv_bfloat162*)(g_hlo + base))[0] = __nv_bfloat162(lo[0], lo[1]);
    ((__nv_bfloat162*)(g_hlo + base))[1] = __nv_bfloat162(lo[2], lo[3]);
    float sum = h[0] + h[1] + h[2] + h[3];
    #pragma unroll
    for (int o = 16; o; o >>= 1) sum += __shfl_xor_sync(0xFFFFFFFFu, sum, o);
    if (lane == 0) g_S1[pid][g] = sum;
}

// ---------------------------------------------------------------------------
__device__ __forceinline__ void mma_bf16(float c[4],
    uint32_t a0, uint32_t a1, uint32_t a2, uint32_t a3, uint32_t b0, uint32_t b1)
{
    asm volatile(
        "mma.sync.aligned.m16n8k16.row.col.f32.bf16.bf16.f32 "
        "{%0,%1,%2,%3}, {%4,%5,%6,%7}, {%8,%9}, {%0,%1,%2,%3};\n"
        : "+f"(c[0]), "+f"(c[1]), "+f"(c[2]), "+f"(c[3])
        : "r"(a0), "r"(a1), "r"(a2), "r"(a3), "r"(b0), "r"(b1));
}

// ---------------------------------------------------------------------------
// Tensor-core dequant GEMM.
//   out[t][r] = sum_g s_{r,g} * P'_{t,r,g} + (z_{r,g} - 128 s_{r,g}) * S_{t,g}
//   P' via bf16 MMA with weights (q+128) exact in bf16 and x split hi/lo.
// Block: 64 tokens (M) x 128 rows (N) x 64 k-chunk. 8 warps of 32x32.
// ---------------------------------------------------------------------------
template <int PHASE>
__global__ void __launch_bounds__(256)
mma_gemm(const uint8_t* __restrict__ wpk,
         const float* __restrict__ pa,
         const float* __restrict__ pb)
{
    constexpr int RTOT  = PHASE ? HID   : TWO_I;
    constexpr int INF   = PHASE ? INTER : HID;
    constexpr int NGRP  = INF / GSIZE;       // 32 or 16
    constexpr int INFH  = INF / 2;
    constexpr int SHIFT = PHASE ? 0 : 1;

    const int e     = blockIdx.y;
    const int n_tok = g_cnt[e];
    const int t0    = blockIdx.z * 64;
    if (t0 >= n_tok) return;
    const int r0   = blockIdx.x * 128;
    const int tid  = threadIdx.x;
    const int lane = tid & 31;
    const int wid  = tid >> 5;
    const int warp_m = wid & 1;              // 2 warps over 64 tokens
    const int warp_n = wid >> 1;             // 4 warps over 128 rows
    const int trow = lane >> 2;              // 0..7
    const int tcol = (lane & 3) * 2;         // 0,2,4,6

    const int swp = PHASE ? g_swap_dn : g_swap_gu;
    const float* __restrict__ sc = swp ? pb : pa;
    const float* __restrict__ zp = swp ? pa : pb;
    const int wmode = g_wmode;

    __shared__ __align__(16) char SB[37888];
    __nv_bfloat16* Ahi = (__nv_bfloat16*)(SB);           // [64][72]
    __nv_bfloat16* Alo = (__nv_bfloat16*)(SB + 9216);    // [64][72]
    __nv_bfloat16* Wsm = (__nv_bfloat16*)(SB + 18432);   // [128][72]
    float*         s_scale = (float*)(SB + 36864);       // [128]
    int*           s_pid   = (int*)(SB + 37376);         // [64]
    // prologue aliases (released before first main-loop chunk)
    float* Ssm = (float*)(SB);                            // [64][NGRP]
    float* Zsm = (float*)(SB + 8192);                     // [128][NGRP]

    const __nv_bfloat16* __restrict__ Ahg = PHASE ? g_hhi : g_xhi;
    const __nv_bfloat16* __restrict__ Alg = PHASE ? g_hlo : g_xlo;
    const float* __restrict__ Sglob = PHASE ? &g_S1[0][0] : &g_S0[0][0];
    float* __restrict__ C = PHASE ? g_dn : g_gu;

    if (tid < 64) {
        int slot = t0 + tid;
        s_pid[tid] = (slot < n_tok) ? g_list[e][slot] : -1;
    }
    __syncthreads();

    const size_t wrowbase = (size_t)e * RTOT + r0;

    // ---- prologue staging: S (tokens x groups), z' = z - 128 s (rows x groups)
    for (int i = tid; i < 64 * NGRP; i += 256) {
        int t = i / NGRP, g = i % NGRP;
        int p = s_pid[t];
        Ssm[i] = (p >= 0) ? Sglob[(size_t)(p >> SHIFT) * NGRP + g] : 0.f;
    }
    for (int i = tid; i < 128 * NGRP; i += 256) {
        int r = i / NGRP, g = i % NGRP;
        size_t idx = (wrowbase + r) * NGRP + g;
        Zsm[i] = zp[idx] - 128.f * sc[idx];
    }
    __syncthreads();

    float cT[2][4][4], cG[2][4][4];
    #pragma unroll
    for (int m = 0; m < 2; m++)
        #pragma unroll
        for (int n = 0; n < 4; n++)
            #pragma unroll
            for (int k = 0; k < 4; k++) { cT[m][n][k] = 0.f; cG[m][n][k] = 0.f; }

    // ---- zero-point term: cT[t][r] = sum_g S[t][g] * z'[r][g]
    #pragma unroll 4
    for (int g = 0; g < NGRP; g++) {
        float sv[2][2];
        #pragma unroll
        for (int m = 0; m < 2; m++) {
            int tl = warp_m * 32 + m * 16 + trow;
            sv[m][0] = Ssm[tl * NGRP + g];
            sv[m][1] = Ssm[(tl + 8) * NGRP + g];
        }
        #pragma unroll
        for (int n = 0; n < 4; n++) {
            int rr = warp_n * 32 + n * 8 + tcol;
            float z0 = Zsm[rr * NGRP + g];
            float z1 = Zsm[(rr + 1) * NGRP + g];
            #pragma unroll
            for (int m = 0; m < 2; m++) {
                cT[m][n][0] += sv[m][0] * z0;
                cT[m][n][1] += sv[m][0] * z1;
                cT[m][n][2] += sv[m][1] * z0;
                cT[m][n][3] += sv[m][1] * z1;
            }
        }
    }

    // ---- main loop over k-chunks of 64 ----
    for (int h0 = 0; h0 < INF; h0 += 64) {
        __syncthreads();   // prologue / previous-chunk MMAs done

        // activations: 64 tokens x 64 k, hi + lo, uint4 (8 bf16) per load
        #pragma unroll
        for (int i = 0; i < 2; i++) {
            int idx = tid + i * 256;        // 0..511
            int t   = idx >> 3;
            int k8  = (idx & 7) * 8;
            int p   = s_pid[t];
            uint4 vh = make_uint4(0, 0, 0, 0), vl = make_uint4(0, 0, 0, 0);
            if (p >= 0) {
                size_t off = (size_t)(p >> SHIFT) * INF + h0 + k8;
                vh = *(const uint4*)(Ahg + off);
                vl = *(const uint4*)(Alg + off);
            }
            *(uint4*)(Ahi + t * 72 + k8) = vh;
            *(uint4*)(Alo + t * 72 + k8) = vl;
        }

        // weights: 128 rows x 64 k -> (q+128) bf16 via bit trick
        #pragma unroll
        for (int i = 0; i < 4; i++) {
            int idx = tid + i * 256;        // 0..1023
            int r = idx >> 3;
            int b = idx & 7;
            size_t eoff = (wrowbase + r) * INFH + (h0 >> 1) + b * 4;
            uint32_t bytes4;
            if (wmode == 0) {
                bytes4 = *(const uint32_t*)(wpk + eoff);
            } else {
                uint4 v4 = *(const uint4*)((const uint32_t*)wpk + eoff);
                bytes4 = (v4.x & 0xFFu) | ((v4.y & 0xFFu) << 8)
                       | ((v4.z & 0xFFu) << 16) | ((v4.w & 0xFFu) << 24);
            }
            #pragma unroll
            for (int j = 0; j < 4; j++) {
                uint32_t byte = (bytes4 >> (8 * j)) & 0xFFu;
                // bf16(128+q) = 0x4300 | q ; even col = high nibble, odd = low
                uint32_t pair = 0x43004300u | (byte >> 4) | ((byte & 15u) << 16);
                *(uint32_t*)(Wsm + r * 72 + b * 8 + j * 2) = pair;
            }
        }

        if ((h0 & 127) == 0 && tid < 128)
            s_scale[tid] = sc[(wrowbase + tid) * NGRP + (h0 >> 7)];
        __syncthreads();

        #pragma unroll
        for (int ks = 0; ks < 4; ks++) {
            const int kb = ks * 16;
            uint32_t b[4][2];
            #pragma unroll
            for (int n = 0; n < 4; n++) {
                int rr = warp_n * 32 + n * 8 + trow;
                b[n][0] = *(const uint32_t*)(Wsm + rr * 72 + kb + tcol);
                b[n][1] = *(const uint32_t*)(Wsm + rr * 72 + kb + tcol + 8);
            }
            #pragma unroll
            for (int hl = 0; hl < 2; hl++) {
                const __nv_bfloat16* As = hl ? Alo : Ahi;
                #pragma unroll
                for (int m = 0; m < 2; m++) {
                    int tr = warp_m * 32 + m * 16 + trow;
                    uint32_t a0 = *(const uint32_t*)(As + tr * 72 + kb + tcol);
                    uint32_t a1 = *(const uint32_t*)(As + (tr + 8) * 72 + kb + tcol);
                    uint32_t a2 = *(const uint32_t*)(As + tr * 72 + kb + tcol + 8);
                    uint32_t a3 = *(const uint32_t*)(As + (tr + 8) * 72 + kb + tcol + 8);
                    #pragma unroll
                    for (int n = 0; n < 4; n++)
                        mma_bf16(cG[m][n], a0, a1, a2, a3, b[n][0], b[n][1]);
                }
            }
        }

        // group boundary: fold s_g * P'_g into totals
        if (((h0 + 64) & 127) == 0) {
            #pragma unroll
            for (int n = 0; n < 4; n++) {
                int rr = warp_n * 32 + n * 8 + tcol;
                float s0 = s_scale[rr];
                float s1 = s_scale[rr + 1];
                #pragma unroll
                for (int m = 0; m < 2; m++) {
                    cT[m][n][0] += s0 * cG[m][n][0];
                    cT[m][n][1] += s1 * cG[m][n][1];
                    cT[m][n][2] += s0 * cG[m][n][2];
                    cT[m][n][3] += s1 * cG[m][n][3];
                    cG[m][n][0] = 0.f; cG[m][n][1] = 0.f;
                    cG[m][n][2] = 0.f; cG[m][n][3] = 0.f;
                }
            }
        }
    }

    // ---- store ----
    #pragma unroll
    for (int m = 0; m < 2; m++) {
        #pragma unroll
        for (int half = 0; half < 2; half++) {
            int tl = warp_m * 32 + m * 16 + trow + half * 8;
            int p = s_pid[tl];
            if (p < 0) continue;
            float cf = PHASE ? g_coef[p] : 1.f;
            float* Crow = C + (size_t)p * RTOT + r0;
            #pragma unroll
            for (int n = 0; n < 4; n++) {
                int rr = warp_n * 32 + n * 8 + tcol;
                float2 v;
                v.x = cT[m][n][half * 2 + 0] * cf;
                v.y = cT[m][n][half * 2 + 1] * cf;
                *(float2*)(Crow + rr) = v;
            }
        }
    }
}

// ---------------------------------------------------------------------------
__global__ void k_comb(float* __restrict__ out) {
    int i = blockIdx.x * blockDim.x + threadIdx.x;
    if (i >= TOK * HID) return;
    int t = i >> 11;
    int c = i & (HID - 1);
    out[i] = g_dn[(size_t)(2 * t) * HID + c] + g_dn[(size_t)(2 * t + 1) * HID + c];
}

// ---------------------------------------------------------------------------
extern "C" void kernel_launch(void* const* d_in, const int* in_sizes, int n_in,
                              void* d_out, int out_size)
{
    (void)out_size;
    int ix = 0, igup = 1, igs_a = 2, igs_b = 3, idnp = 4, ids_a = 5, ids_b = 6,
        irt_a = 7, irt_b = 8;

    int gu_pair[2] = {-1, -1}, dn_pair[2] = {-1, -1}, rt_pair[2] = {-1, -1};
    int f_x = -1, f_gup = -1, f_dnp = -1;
    for (int i = 0; i < n_in; i++) {
        long long s = in_sizes[i];
        if      (s == 2097152LL)  f_x = i;
        else if (s == 67108864LL) f_gup = i;
        else if (s == 33554432LL) f_dnp = i;
        else if (s == 1048576LL)  { if (gu_pair[0] < 0) gu_pair[0] = i; else gu_pair[1] = i; }
        else if (s == 524288LL)   { if (dn_pair[0] < 0) dn_pair[0] = i; else dn_pair[1] = i; }
        else if (s == 2048LL)     { if (rt_pair[0] < 0) rt_pair[0] = i; else rt_pair[1] = i; }
    }
    if (f_x >= 0 && f_gup >= 0 && f_dnp >= 0 &&
        gu_pair[1] >= 0 && dn_pair[1] >= 0 && rt_pair[1] >= 0) {
        ix = f_x; igup = f_gup; idnp = f_dnp;
        igs_a = gu_pair[0]; igs_b = gu_pair[1];
        ids_a = dn_pair[0]; ids_b = dn_pair[1];
        irt_a = rt_pair[0]; irt_b = rt_pair[1];
    }

    const float*   x    = (const float*)  d_in[ix];
    const uint8_t* gu_p = (const uint8_t*)d_in[igup];
    const float*   gu_a = (const float*)  d_in[igs_a];
    const float*   gu_b = (const float*)  d_in[igs_b];
    const uint8_t* dn_p = (const uint8_t*)d_in[idnp];
    const float*   dn_a = (const float*)  d_in[ids_a];
    const float*   dn_b = (const float*)  d_in[ids_b];
    const void*    rt_a = d_in[irt_a];
    const void*    rt_b = d_in[irt_b];
    float*         out  = (float*)        d_out;

    k_detect<<<1, 32>>>((const uint32_t*)gu_p, gu_a, dn_a, (const uint32_t*)rt_a);
    k_zero<<<1, 32>>>();
    k_route<<<NPAIR / 256, 256>>>(rt_a, rt_b);
    k_split<<<TOK * (HID / GSIZE) / 8, 256>>>(x);

    dim3 g0(TWO_I / 128, EXPERTS, NPAIR / 64);   // (64, 8, 32)
    mma_gemm<0><<<g0, 256>>>(gu_p, gu_a, gu_b);

    k_gelu<<<NPAIR * (INTER / GSIZE) / 8, 256>>>();

    dim3 g1(HID / 128, EXPERTS, NPAIR / 64);     // (16, 8, 32)
    mma_gemm<1><<<g1, 256>>>(dn_p, dn_a, dn_b);

    k_comb<<<(TOK * HID) / 256, 256>>>(out);
}

// round 4
// speedup vs baseline: 3.5113x; 1.2029x over previous
#include <cuda_runtime.h>
#include <cuda_bf16.h>
#include <cstdint>

#define EXPERTS 8
#define HID     2048
#define INTER   4096
#define TWO_I   8192
#define TOK     1024
#define NPAIR   2048
#define GSIZE   128

// ---------------------------------------------------------------------------
// Scratch (static __device__ globals)
// ---------------------------------------------------------------------------
__device__ float         g_gu [(size_t)NPAIR * TWO_I];
__device__ __nv_bfloat16 g_hhi[(size_t)NPAIR * INTER];
__device__ __nv_bfloat16 g_hlo[(size_t)NPAIR * INTER];
__device__ __nv_bfloat16 g_xhi[(size_t)TOK * HID];
__device__ __nv_bfloat16 g_xlo[(size_t)TOK * HID];
__device__ float         g_S0[TOK][HID / GSIZE];
__device__ float         g_S1[NPAIR][INTER / GSIZE];
__device__ float         g_dn[(size_t)NPAIR * HID];
__device__ int   g_cnt[EXPERTS];
__device__ int   g_list[EXPERTS][NPAIR];
__device__ float g_coef[NPAIR];

__device__ int g_wmode, g_swap_gu, g_swap_dn, g_swap_rt;

// ---------------------------------------------------------------------------
__global__ void k_detect(const uint32_t* __restrict__ gup,
                         const float* __restrict__ gus_a,
                         const float* __restrict__ dns_a,
                         const uint32_t* __restrict__ rt_a)
{
    if (threadIdx.x != 0) return;
    int widened = 1;
    for (int i = 0; i < 16; i++)
        if (gup[i] & 0xFFFFFF00u) widened = 0;
    g_wmode = widened;
    int neg = 0;
    for (int i = 0; i < 9; i++) neg += (gus_a[i] < 0.f) ? 1 : 0;
    g_swap_gu = (neg > 4) ? 1 : 0;
    neg = 0;
    for (int i = 0; i < 9; i++) neg += (dns_a[i] < 0.f) ? 1 : 0;
    g_swap_dn = (neg > 4) ? 1 : 0;
    int small = 1;
    for (int i = 0; i < 16; i++)
        if (rt_a[i] >= 256u) small = 0;
    g_swap_rt = small ? 0 : 1;
}

__global__ void k_zero() {
    if (threadIdx.x < EXPERTS) g_cnt[threadIdx.x] = 0;
}

__global__ void k_route(const void* __restrict__ a, const void* __restrict__ b) {
    const int*   ridx = (const int*)  (g_swap_rt ? b : a);
    const float* rw   = (const float*)(g_swap_rt ? a : b);
    int i = blockIdx.x * blockDim.x + threadIdx.x;
    if (i >= NPAIR) return;
    int e = ridx[i];
    int pos = atomicAdd(&g_cnt[e], 1);
    g_list[e][pos] = i;
    g_coef[i] = rw[i];
}

// ---------------------------------------------------------------------------
__global__ void k_split(const float* __restrict__ x) {
    int wg   = blockIdx.x * 8 + (threadIdx.x >> 5);
    int lane = threadIdx.x & 31;
    int token = wg >> 4;
    int g     = wg & 15;
    size_t base = (size_t)token * HID + g * GSIZE + lane * 4;
    float4 v = *(const float4*)(x + base);
    __nv_bfloat16 h0 = __float2bfloat16(v.x), h1 = __float2bfloat16(v.y);
    __nv_bfloat16 h2 = __float2bfloat16(v.z), h3 = __float2bfloat16(v.w);
    __nv_bfloat16 l0 = __float2bfloat16(v.x - __bfloat162float(h0));
    __nv_bfloat16 l1 = __float2bfloat16(v.y - __bfloat162float(h1));
    __nv_bfloat16 l2 = __float2bfloat16(v.z - __bfloat162float(h2));
    __nv_bfloat16 l3 = __float2bfloat16(v.w - __bfloat162float(h3));
    ((__nv_bfloat162*)(g_xhi + base))[0] = __nv_bfloat162(h0, h1);
    ((__nv_bfloat162*)(g_xhi + base))[1] = __nv_bfloat162(h2, h3);
    ((__nv_bfloat162*)(g_xlo + base))[0] = __nv_bfloat162(l0, l1);
    ((__nv_bfloat162*)(g_xlo + base))[1] = __nv_bfloat162(l2, l3);
    float sum = v.x + v.y + v.z + v.w;
    #pragma unroll
    for (int o = 16; o; o >>= 1) sum += __shfl_xor_sync(0xFFFFFFFFu, sum, o);
    if (lane == 0) g_S0[token][g] = sum;
}

// ---------------------------------------------------------------------------
__global__ void k_gelu() {
    int wg   = blockIdx.x * 8 + (threadIdx.x >> 5);
    int lane = threadIdx.x & 31;
    int pid = wg >> 5;
    int g   = wg & 31;
    size_t base = (size_t)pid * INTER + g * GSIZE + lane * 4;
    size_t gub  = (size_t)pid * TWO_I + g * GSIZE + lane * 4;
    float4 gg = *(const float4*)(g_gu + gub);
    float4 uu = *(const float4*)(g_gu + gub + INTER);
    float h[4];
    float gv[4] = {gg.x, gg.y, gg.z, gg.w};
    float uv[4] = {uu.x, uu.y, uu.z, uu.w};
    #pragma unroll
    for (int i = 0; i < 4; i++) {
        float t = tanhf(0.7978845608028654f * (gv[i] + 0.044715f * gv[i] * gv[i] * gv[i]));
        h[i] = 0.5f * gv[i] * (1.f + t) * uv[i];
    }
    __nv_bfloat16 hi[4], lo[4];
    #pragma unroll
    for (int i = 0; i < 4; i++) {
        hi[i] = __float2bfloat16(h[i]);
        lo[i] = __float2bfloat16(h[i] - __bfloat162float(hi[i]));
    }
    ((__nv_bfloat162*)(g_hhi + base))[0] = __nv_bfloat162(hi[0], hi[1]);
    ((__nv_bfloat162*)(g_hhi + base))[1] = __nv_bfloat162(hi[2], hi[3]);
    ((__nv_bfloat162*)(g_hlo + base))[0] = __nv_bfloat162(lo[0], lo[1]);
    ((__nv_bfloat162*)(g_hlo + base))[1] = __nv_bfloat162(lo[2], lo[3]);
    float sum = h[0] + h[1] + h[2] + h[3];
    #pragma unroll
    for (int o = 16; o; o >>= 1) sum += __shfl_xor_sync(0xFFFFFFFFu, sum, o);
    if (lane == 0) g_S1[pid][g] = sum;
}

// ---------------------------------------------------------------------------
__device__ __forceinline__ void mma_bf16(float c[4],
    uint32_t a0, uint32_t a1, uint32_t a2, uint32_t a3, uint32_t b0, uint32_t b1)
{
    asm volatile(
        "mma.sync.aligned.m16n8k16.row.col.f32.bf16.bf16.f32 "
        "{%0,%1,%2,%3}, {%4,%5,%6,%7}, {%8,%9}, {%0,%1,%2,%3};\n"
        : "+f"(c[0]), "+f"(c[1]), "+f"(c[2]), "+f"(c[3])
        : "r"(a0), "r"(a1), "r"(a2), "r"(a3), "r"(b0), "r"(b1));
}

__device__ __forceinline__ uint32_t smaddr(const void* p) {
    return (uint32_t)__cvta_generic_to_shared(p);
}
__device__ __forceinline__ void cp16(uint32_t dst, const void* src, int srcbytes) {
    asm volatile("cp.async.cg.shared.global [%0], [%1], 16, %2;"
                 :: "r"(dst), "l"(src), "r"(srcbytes));
}
__device__ __forceinline__ void cp4(uint32_t dst, const void* src) {
    asm volatile("cp.async.ca.shared.global [%0], [%1], 4;"
                 :: "r"(dst), "l"(src));
}
__device__ __forceinline__ void ldsm4(uint32_t& a0, uint32_t& a1,
                                      uint32_t& a2, uint32_t& a3, uint32_t addr) {
    asm volatile("ldmatrix.sync.aligned.m8n8.x4.shared.b16 {%0,%1,%2,%3}, [%4];"
                 : "=r"(a0), "=r"(a1), "=r"(a2), "=r"(a3) : "r"(addr));
}

// ---------------------------------------------------------------------------
// Pipelined tensor-core dequant GEMM.
// Block: 64 tokens x 128 rows x 64-k chunks, 8 warps (2m x 4n).
// 2-stage cp.async pipeline; weights staged as raw packed nibbles (XOR-swizzled
// u32 words), dequantized to bf16 (q+128, exact) in registers at fragment time.
// ---------------------------------------------------------------------------
template <int PHASE>
__global__ void __launch_bounds__(256, 2)
mma_gemm(const uint8_t* __restrict__ wpk,
         const float* __restrict__ pa,
         const float* __restrict__ pb)
{
    constexpr int RTOT  = PHASE ? HID   : TWO_I;
    constexpr int INF   = PHASE ? INTER : HID;
    constexpr int NGRP  = INF / GSIZE;
    constexpr int INFH  = INF / 2;
    constexpr int SHIFT = PHASE ? 0 : 1;
    constexpr int NCHUNK = INF / 64;
    constexpr int STG = 22528;            // Ahi 9216 + Alo 9216 + W 4096

    const int e     = blockIdx.y;
    const int n_tok = g_cnt[e];
    const int t0    = blockIdx.z * 64;
    if (t0 >= n_tok) return;
    const int r0   = blockIdx.x * 128;
    const int tid  = threadIdx.x;
    const int lane = tid & 31;
    const int wid  = tid >> 5;
    const int warp_m = wid & 1;
    const int warp_n = wid >> 1;
    const int trow = lane >> 2;
    const int tcol = (lane & 3) * 2;
    const int bsh  = 8 * (lane & 3);      // byte shift for B dequant

    const int swp = PHASE ? g_swap_dn : g_swap_gu;
    const float* __restrict__ sc = swp ? pb : pa;
    const float* __restrict__ zp = swp ? pa : pb;
    const int wmode = g_wmode;

    extern __shared__ __align__(16) char sm[];
    char*  st0   = sm;
    char*  st1   = sm + STG;
    float* Ssm   = (float*)(sm + 2 * STG);
    float* Zsm   = Ssm + 64 * NGRP;
    float* Ssc   = Zsm + 128 * NGRP;
    int*   s_pid = (int*)(Ssc + 128 * NGRP);

    const __nv_bfloat16* __restrict__ Ahg = PHASE ? g_hhi : g_xhi;
    const __nv_bfloat16* __restrict__ Alg = PHASE ? g_hlo : g_xlo;
    const float* __restrict__ Sglob = PHASE ? &g_S1[0][0] : &g_S0[0][0];
    float* __restrict__ C = PHASE ? g_dn : g_gu;

    if (tid < 64) {
        int slot = t0 + tid;
        s_pid[tid] = (slot < n_tok) ? g_list[e][slot] : -1;
    }
    __syncthreads();

    const size_t wrowbase = (size_t)e * RTOT + r0;

    // ---- async prefetch of one chunk into stage buffer ----
    auto prefetch = [&](char* S, int h0) {
        #pragma unroll
        for (int i = 0; i < 2; i++) {
            int idx = tid + i * 256;          // 0..511
            int t   = idx >> 3;
            int seg = idx & 7;
            int p   = s_pid[t];
            int sz  = (p >= 0) ? 16 : 0;
            size_t off = (p >= 0) ? ((size_t)(p >> SHIFT) * INF + h0 + seg * 8) : 0;
            cp16(smaddr(S + t * 144 + seg * 16), Ahg + off, sz);
            cp16(smaddr(S + 9216 + t * 144 + seg * 16), Alg + off, sz);
        }
        uint32_t* W = (uint32_t*)(S + 18432);
        if (wmode == 0) {
            #pragma unroll
            for (int i = 0; i < 4; i++) {
                int idx = tid + i * 256;      // 0..1023
                int row = idx >> 3;
                int wc  = idx & 7;
                const uint8_t* src = wpk + (wrowbase + row) * INFH + (h0 >> 1) + wc * 4;
                cp4(smaddr(W + row * 8 + (wc ^ (row & 7))), src);
            }
        } else {
            #pragma unroll
            for (int i = 0; i < 4; i++) {
                int idx = tid + i * 256;
                int row = idx >> 3;
                int wc  = idx & 7;
                size_t eoff = (wrowbase + row) * INFH + (h0 >> 1) + wc * 4;
                uint4 v4 = *(const uint4*)((const uint32_t*)wpk + eoff);
                W[row * 8 + (wc ^ (row & 7))] =
                    (v4.x & 0xFFu) | ((v4.y & 0xFFu) << 8)
                  | ((v4.z & 0xFFu) << 16) | ((v4.w & 0xFFu) << 24);
            }
        }
    };

    // kick off stage 0 while we do the fp32 prologue
    prefetch(st0, 0);
    asm volatile("cp.async.commit_group;");

    // ---- prologue: S (tokens x groups), z' = z - 128 s, and scale table ----
    for (int i = tid; i < 64 * NGRP; i += 256) {
        int t = i / NGRP, g = i % NGRP;
        int p = s_pid[t];
        Ssm[i] = (p >= 0) ? Sglob[(size_t)(p >> SHIFT) * NGRP + g] : 0.f;
    }
    for (int i = tid; i < 128 * NGRP; i += 256) {
        int r = i / NGRP, g = i % NGRP;
        size_t idx = (wrowbase + r) * NGRP + g;
        float s = sc[idx];
        Zsm[i] = zp[idx] - 128.f * s;
        Ssc[i] = s;
    }
    __syncthreads();

    float cT[2][4][4], cG[2][4][4];
    #pragma unroll
    for (int m = 0; m < 2; m++)
        #pragma unroll
        for (int n = 0; n < 4; n++)
            #pragma unroll
            for (int k = 0; k < 4; k++) { cT[m][n][k] = 0.f; cG[m][n][k] = 0.f; }

    // zero-point term: cT[t][r] = sum_g S[t][g] * z'[r][g]
    #pragma unroll 4
    for (int g = 0; g < NGRP; g++) {
        float sv[2][2];
        #pragma unroll
        for (int m = 0; m < 2; m++) {
            int tl = warp_m * 32 + m * 16 + trow;
            sv[m][0] = Ssm[tl * NGRP + g];
            sv[m][1] = Ssm[(tl + 8) * NGRP + g];
        }
        #pragma unroll
        for (int n = 0; n < 4; n++) {
            int rr = warp_n * 32 + n * 8 + tcol;
            float z0 = Zsm[rr * NGRP + g];
            float z1 = Zsm[(rr + 1) * NGRP + g];
            #pragma unroll
            for (int m = 0; m < 2; m++) {
                cT[m][n][0] += sv[m][0] * z0;
                cT[m][n][1] += sv[m][0] * z1;
                cT[m][n][2] += sv[m][1] * z0;
                cT[m][n][3] += sv[m][1] * z1;
            }
        }
    }

    // ldmatrix per-lane element offset within a 16x16 A tile
    const int lmat = lane >> 3;
    const int lm_off = (((lmat & 1) * 8 + (lane & 7)) * 72 + (lmat >> 1) * 8);

    // ---- main pipelined loop ----
    for (int c = 0; c < NCHUNK; c++) {
        __syncthreads();     // all warps done with the buffer we are about to refill
        if (c + 1 < NCHUNK)
            prefetch((c + 1) & 1 ? st1 : st0, (c + 1) * 64);
        asm volatile("cp.async.commit_group;");
        asm volatile("cp.async.wait_group 1;");
        __syncthreads();     // stage c visible to all warps

        char* S = (c & 1) ? st1 : st0;
        const __nv_bfloat16* Ahi = (const __nv_bfloat16*)S;
        const __nv_bfloat16* Alo = (const __nv_bfloat16*)(S + 9216);
        const uint32_t*      W   = (const uint32_t*)(S + 18432);

        #pragma unroll
        for (int ks = 0; ks < 4; ks++) {
            const int kb = ks * 16;
            // B fragments: raw bytes -> bf16(q+128) in registers
            uint32_t bfrag[4][2];
            #pragma unroll
            for (int n = 0; n < 4; n++) {
                int rr = warp_n * 32 + n * 8 + trow;
                uint32_t w0 = W[rr * 8 + ((2 * ks)     ^ trow)];
                uint32_t w1 = W[rr * 8 + ((2 * ks + 1) ^ trow)];
                uint32_t b0 = (w0 >> bsh) & 0xFFu;
                uint32_t b1 = (w1 >> bsh) & 0xFFu;
                bfrag[n][0] = 0x43004300u | (b0 >> 4) | ((b0 & 15u) << 16);
                bfrag[n][1] = 0x43004300u | (b1 >> 4) | ((b1 & 15u) << 16);
            }
            #pragma unroll
            for (int hl = 0; hl < 2; hl++) {
                const __nv_bfloat16* As = hl ? Alo : Ahi;
                #pragma unroll
                for (int m = 0; m < 2; m++) {
                    uint32_t addr = smaddr(As + (warp_m * 32 + m * 16) * 72 + kb + lm_off);
                    uint32_t a0, a1, a2, a3;
                    ldsm4(a0, a1, a2, a3, addr);
                    #pragma unroll
                    for (int n = 0; n < 4; n++)
                        mma_bf16(cG[m][n], a0, a1, a2, a3, bfrag[n][0], bfrag[n][1]);
                }
            }
        }

        // group boundary (every 128 k = 2 chunks): fold s_g * P'_g
        if (c & 1) {
            int g = c >> 1;
            #pragma unroll
            for (int n = 0; n < 4; n++) {
                int rr = warp_n * 32 + n * 8 + tcol;
                float s0 = Ssc[rr * NGRP + g];
                float s1 = Ssc[(rr + 1) * NGRP + g];
                #pragma unroll
                for (int m = 0; m < 2; m++) {
                    cT[m][n][0] += s0 * cG[m][n][0];
                    cT[m][n][1] += s1 * cG[m][n][1];
                    cT[m][n][2] += s0 * cG[m][n][2];
                    cT[m][n][3] += s1 * cG[m][n][3];
                    cG[m][n][0] = 0.f; cG[m][n][1] = 0.f;
                    cG[m][n][2] = 0.f; cG[m][n][3] = 0.f;
                }
            }
        }
    }

    // ---- store ----
    #pragma unroll
    for (int m = 0; m < 2; m++) {
        #pragma unroll
        for (int half = 0; half < 2; half++) {
            int tl = warp_m * 32 + m * 16 + trow + half * 8;
            int p = s_pid[tl];
            if (p < 0) continue;
            float cf = PHASE ? g_coef[p] : 1.f;
            float* Crow = C + (size_t)p * RTOT + r0;
            #pragma unroll
            for (int n = 0; n < 4; n++) {
                int rr = warp_n * 32 + n * 8 + tcol;
                float2 v;
                v.x = cT[m][n][half * 2 + 0] * cf;
                v.y = cT[m][n][half * 2 + 1] * cf;
                *(float2*)(Crow + rr) = v;
            }
        }
    }
}

// ---------------------------------------------------------------------------
__global__ void k_comb(float* __restrict__ out) {
    int i = blockIdx.x * blockDim.x + threadIdx.x;
    if (i >= TOK * HID) return;
    int t = i >> 11;
    int c = i & (HID - 1);
    out[i] = g_dn[(size_t)(2 * t) * HID + c] + g_dn[(size_t)(2 * t + 1) * HID + c];
}

// ---------------------------------------------------------------------------
extern "C" void kernel_launch(void* const* d_in, const int* in_sizes, int n_in,
                              void* d_out, int out_size)
{
    (void)out_size;
    int ix = 0, igup = 1, igs_a = 2, igs_b = 3, idnp = 4, ids_a = 5, ids_b = 6,
        irt_a = 7, irt_b = 8;

    int gu_pair[2] = {-1, -1}, dn_pair[2] = {-1, -1}, rt_pair[2] = {-1, -1};
    int f_x = -1, f_gup = -1, f_dnp = -1;
    for (int i = 0; i < n_in; i++) {
        long long s = in_sizes[i];
        if      (s == 2097152LL)  f_x = i;
        else if (s == 67108864LL) f_gup = i;
        else if (s == 33554432LL) f_dnp = i;
        else if (s == 1048576LL)  { if (gu_pair[0] < 0) gu_pair[0] = i; else gu_pair[1] = i; }
        else if (s == 524288LL)   { if (dn_pair[0] < 0) dn_pair[0] = i; else dn_pair[1] = i; }
        else if (s == 2048LL)     { if (rt_pair[0] < 0) rt_pair[0] = i; else rt_pair[1] = i; }
    }
    if (f_x >= 0 && f_gup >= 0 && f_dnp >= 0 &&
        gu_pair[1] >= 0 && dn_pair[1] >= 0 && rt_pair[1] >= 0) {
        ix = f_x; igup = f_gup; idnp = f_dnp;
        igs_a = gu_pair[0]; igs_b = gu_pair[1];
        ids_a = dn_pair[0]; ids_b = dn_pair[1];
        irt_a = rt_pair[0]; irt_b = rt_pair[1];
    }

    const float*   x    = (const float*)  d_in[ix];
    const uint8_t* gu_p = (const uint8_t*)d_in[igup];
    const float*   gu_a = (const float*)  d_in[igs_a];
    const float*   gu_b = (const float*)  d_in[igs_b];
    const uint8_t* dn_p = (const uint8_t*)d_in[idnp];
    const float*   dn_a = (const float*)  d_in[ids_a];
    const float*   dn_b = (const float*)  d_in[ids_b];
    const void*    rt_a = d_in[irt_a];
    const void*    rt_b = d_in[irt_b];
    float*         out  = (float*)        d_out;

    // dynamic smem: stages + prologue tables
    const int SMEM0 = 2 * 22528 + (64 + 128 + 128) * (HID / GSIZE) * 4 + 256;   // 65792
    const int SMEM1 = 2 * 22528 + (64 + 128 + 128) * (INTER / GSIZE) * 4 + 256; // 86272
    cudaFuncSetAttribute(mma_gemm<0>, cudaFuncAttributeMaxDynamicSharedMemorySize, SMEM0);
    cudaFuncSetAttribute(mma_gemm<1>, cudaFuncAttributeMaxDynamicSharedMemorySize, SMEM1);

    k_detect<<<1, 32>>>((const uint32_t*)gu_p, gu_a, dn_a, (const uint32_t*)rt_a);
    k_zero<<<1, 32>>>();
    k_route<<<NPAIR / 256, 256>>>(rt_a, rt_b);
    k_split<<<TOK * (HID / GSIZE) / 8, 256>>>(x);

    dim3 g0(TWO_I / 128, EXPERTS, NPAIR / 64);   // (64, 8, 32)
    mma_gemm<0><<<g0, 256, SMEM0>>>(gu_p, gu_a, gu_b);

    k_gelu<<<NPAIR * (INTER / GSIZE) / 8, 256>>>();

    dim3 g1(HID / 128, EXPERTS, NPAIR / 64);     // (16, 8, 32)
    mma_gemm<1><<<g1, 256, SMEM1>>>(dn_p, dn_a, dn_b);

    k_comb<<<(TOK * HID) / 256, 256>>>(out);
}

// round 5
// speedup vs baseline: 4.1993x; 1.1959x over previous
#include <cuda_runtime.h>
#include <cuda_bf16.h>
#include <cuda_fp16.h>
#include <cstdint>

#define EXPERTS 8
#define HID     2048
#define INTER   4096
#define TWO_I   8192
#define TOK     1024
#define NPAIR   2048
#define GSIZE   128

// ---------------------------------------------------------------------------
// Scratch (static __device__ globals)
// ---------------------------------------------------------------------------
__device__ float  g_gu[(size_t)NPAIR * TWO_I];
__device__ __half g_hh[(size_t)NPAIR * INTER];   // h rounded to fp16
__device__ __half g_xh[(size_t)TOK * HID];       // x rounded to fp16
__device__ float  g_S0[TOK][HID / GSIZE];        // group sums of fp16(x)
__device__ float  g_S1[NPAIR][INTER / GSIZE];    // group sums of fp16(h)
__device__ float  g_dn[(size_t)NPAIR * HID];
__device__ int    g_cnt[EXPERTS];
__device__ int    g_list[EXPERTS][NPAIR];
__device__ float  g_coef[NPAIR];

__device__ int g_wmode, g_swap_gu, g_swap_dn, g_swap_rt;

// ---------------------------------------------------------------------------
__global__ void k_detect(const uint32_t* __restrict__ gup,
                         const float* __restrict__ gus_a,
                         const float* __restrict__ dns_a,
                         const uint32_t* __restrict__ rt_a)
{
    if (threadIdx.x != 0) return;
    int widened = 1;
    for (int i = 0; i < 16; i++)
        if (gup[i] & 0xFFFFFF00u) widened = 0;
    g_wmode = widened;
    int neg = 0;
    for (int i = 0; i < 9; i++) neg += (gus_a[i] < 0.f) ? 1 : 0;
    g_swap_gu = (neg > 4) ? 1 : 0;
    neg = 0;
    for (int i = 0; i < 9; i++) neg += (dns_a[i] < 0.f) ? 1 : 0;
    g_swap_dn = (neg > 4) ? 1 : 0;
    int small = 1;
    for (int i = 0; i < 16; i++)
        if (rt_a[i] >= 256u) small = 0;
    g_swap_rt = small ? 0 : 1;
}

__global__ void k_zero() {
    if (threadIdx.x < EXPERTS) g_cnt[threadIdx.x] = 0;
}

__global__ void k_route(const void* __restrict__ a, const void* __restrict__ b) {
    const int*   ridx = (const int*)  (g_swap_rt ? b : a);
    const float* rw   = (const float*)(g_swap_rt ? a : b);
    int i = blockIdx.x * blockDim.x + threadIdx.x;
    if (i >= NPAIR) return;
    int e = ridx[i];
    int pos = atomicAdd(&g_cnt[e], 1);
    g_list[e][pos] = i;
    g_coef[i] = rw[i];
}

// ---------------------------------------------------------------------------
// x -> fp16 + group sums of the ROUNDED values (consistency with MMA path).
// ---------------------------------------------------------------------------
__global__ void k_split(const float* __restrict__ x) {
    int wg   = blockIdx.x * 8 + (threadIdx.x >> 5);
    int lane = threadIdx.x & 31;
    int token = wg >> 4;
    int g     = wg & 15;
    size_t base = (size_t)token * HID + g * GSIZE + lane * 4;
    float4 v = *(const float4*)(x + base);
    __half h0 = __float2half_rn(v.x), h1 = __float2half_rn(v.y);
    __half h2 = __float2half_rn(v.z), h3 = __float2half_rn(v.w);
    ((__half2*)(g_xh + base))[0] = __half2(h0, h1);
    ((__half2*)(g_xh + base))[1] = __half2(h2, h3);
    float sum = __half2float(h0) + __half2float(h1)
              + __half2float(h2) + __half2float(h3);
    #pragma unroll
    for (int o = 16; o; o >>= 1) sum += __shfl_xor_sync(0xFFFFFFFFu, sum, o);
    if (lane == 0) g_S0[token][g] = sum;
}

// ---------------------------------------------------------------------------
// gelu(gate)*up in fp32, rounded to fp16; group sums of rounded values.
// ---------------------------------------------------------------------------
__global__ void k_gelu() {
    int wg   = blockIdx.x * 8 + (threadIdx.x >> 5);
    int lane = threadIdx.x & 31;
    int pid = wg >> 5;
    int g   = wg & 31;
    size_t base = (size_t)pid * INTER + g * GSIZE + lane * 4;
    size_t gub  = (size_t)pid * TWO_I + g * GSIZE + lane * 4;
    float4 gg = *(const float4*)(g_gu + gub);
    float4 uu = *(const float4*)(g_gu + gub + INTER);
    float gv[4] = {gg.x, gg.y, gg.z, gg.w};
    float uv[4] = {uu.x, uu.y, uu.z, uu.w};
    __half hh[4];
    float sum = 0.f;
    #pragma unroll
    for (int i = 0; i < 4; i++) {
        float t = tanhf(0.7978845608028654f * (gv[i] + 0.044715f * gv[i] * gv[i] * gv[i]));
        float h = 0.5f * gv[i] * (1.f + t) * uv[i];
        hh[i] = __float2half_rn(h);
        sum += __half2float(hh[i]);
    }
    ((__half2*)(g_hh + base))[0] = __half2(hh[0], hh[1]);
    ((__half2*)(g_hh + base))[1] = __half2(hh[2], hh[3]);
    #pragma unroll
    for (int o = 16; o; o >>= 1) sum += __shfl_xor_sync(0xFFFFFFFFu, sum, o);
    if (lane == 0) g_S1[pid][g] = sum;
}

// ---------------------------------------------------------------------------
__device__ __forceinline__ void mma_f16(float c[4],
    uint32_t a0, uint32_t a1, uint32_t a2, uint32_t a3, uint32_t b0, uint32_t b1)
{
    asm volatile(
        "mma.sync.aligned.m16n8k16.row.col.f32.f16.f16.f32 "
        "{%0,%1,%2,%3}, {%4,%5,%6,%7}, {%8,%9}, {%0,%1,%2,%3};\n"
        : "+f"(c[0]), "+f"(c[1]), "+f"(c[2]), "+f"(c[3])
        : "r"(a0), "r"(a1), "r"(a2), "r"(a3), "r"(b0), "r"(b1));
}

__device__ __forceinline__ uint32_t smaddr(const void* p) {
    return (uint32_t)__cvta_generic_to_shared(p);
}
__device__ __forceinline__ void cp16(uint32_t dst, const void* src, int srcbytes) {
    asm volatile("cp.async.cg.shared.global [%0], [%1], 16, %2;"
                 :: "r"(dst), "l"(src), "r"(srcbytes));
}
__device__ __forceinline__ void cp4(uint32_t dst, const void* src) {
    asm volatile("cp.async.ca.shared.global [%0], [%1], 4;"
                 :: "r"(dst), "l"(src));
}
__device__ __forceinline__ void ldsm4(uint32_t& a0, uint32_t& a1,
                                      uint32_t& a2, uint32_t& a3, uint32_t addr) {
    asm volatile("ldmatrix.sync.aligned.m8n8.x4.shared.b16 {%0,%1,%2,%3}, [%4];"
                 : "=r"(a0), "=r"(a1), "=r"(a2), "=r"(a3) : "r"(addr));
}

// ---------------------------------------------------------------------------
// Pipelined fp16 tensor-core dequant GEMM (single-pass activations).
// Block: 64 tokens x 128 rows x 64-k chunks, 8 warps (2m x 4n).
// Weights staged as raw packed nibbles; dequant to fp16 (q+128, exact) in regs.
// ---------------------------------------------------------------------------
template <int PHASE>
__global__ void __launch_bounds__(256, 2)
mma_gemm(const uint8_t* __restrict__ wpk,
         const float* __restrict__ pa,
         const float* __restrict__ pb)
{
    constexpr int RTOT  = PHASE ? HID   : TWO_I;
    constexpr int INF   = PHASE ? INTER : HID;
    constexpr int NGRP  = INF / GSIZE;
    constexpr int INFH  = INF / 2;
    constexpr int SHIFT = PHASE ? 0 : 1;
    constexpr int NCHUNK = INF / 64;
    constexpr int STG = 13312;            // A 9216 + W 4096

    const int e     = blockIdx.y;
    const int n_tok = g_cnt[e];
    const int t0    = blockIdx.z * 64;
    if (t0 >= n_tok) return;
    const int r0   = blockIdx.x * 128;
    const int tid  = threadIdx.x;
    const int lane = tid & 31;
    const int wid  = tid >> 5;
    const int warp_m = wid & 1;
    const int warp_n = wid >> 1;
    const int trow = lane >> 2;
    const int tcol = (lane & 3) * 2;
    const int bsh  = 8 * (lane & 3);

    const int swp = PHASE ? g_swap_dn : g_swap_gu;
    const float* __restrict__ sc = swp ? pb : pa;
    const float* __restrict__ zp = swp ? pa : pb;
    const int wmode = g_wmode;

    extern __shared__ __align__(16) char sm[];
    char*  st0   = sm;
    char*  st1   = sm + STG;
    float* Ssm   = (float*)(sm + 2 * STG);
    float* Zsm   = Ssm + 64 * NGRP;
    float* Ssc   = Zsm + 128 * NGRP;
    int*   s_pid = (int*)(Ssc + 128 * NGRP);

    const __half* __restrict__ Ag = PHASE ? g_hh : g_xh;
    const float* __restrict__ Sglob = PHASE ? &g_S1[0][0] : &g_S0[0][0];
    float* __restrict__ C = PHASE ? g_dn : g_gu;

    if (tid < 64) {
        int slot = t0 + tid;
        s_pid[tid] = (slot < n_tok) ? g_list[e][slot] : -1;
    }
    __syncthreads();

    const size_t wrowbase = (size_t)e * RTOT + r0;

    // ---- async prefetch of one chunk ----
    auto prefetch = [&](char* S, int h0) {
        #pragma unroll
        for (int i = 0; i < 2; i++) {
            int idx = tid + i * 256;          // 0..511
            int t   = idx >> 3;
            int seg = idx & 7;
            int p   = s_pid[t];
            int sz  = (p >= 0) ? 16 : 0;
            size_t off = (p >= 0) ? ((size_t)(p >> SHIFT) * INF + h0 + seg * 8) : 0;
            cp16(smaddr(S + t * 144 + seg * 16), Ag + off, sz);
        }
        uint32_t* W = (uint32_t*)(S + 9216);
        if (wmode == 0) {
            #pragma unroll
            for (int i = 0; i < 4; i++) {
                int idx = tid + i * 256;      // 0..1023
                int row = idx >> 3;
                int wc  = idx & 7;
                const uint8_t* src = wpk + (wrowbase + row) * INFH + (h0 >> 1) + wc * 4;
                cp4(smaddr(W + row * 8 + (wc ^ (row & 7))), src);
            }
        } else {
            #pragma unroll
            for (int i = 0; i < 4; i++) {
                int idx = tid + i * 256;
                int row = idx >> 3;
                int wc  = idx & 7;
                size_t eoff = (wrowbase + row) * INFH + (h0 >> 1) + wc * 4;
                uint4 v4 = *(const uint4*)((const uint32_t*)wpk + eoff);
                W[row * 8 + (wc ^ (row & 7))] =
                    (v4.x & 0xFFu) | ((v4.y & 0xFFu) << 8)
                  | ((v4.z & 0xFFu) << 16) | ((v4.w & 0xFFu) << 24);
            }
        }
    };

    prefetch(st0, 0);
    asm volatile("cp.async.commit_group;");

    // ---- prologue tables ----
    for (int i = tid; i < 64 * NGRP; i += 256) {
        int t = i / NGRP, g = i % NGRP;
        int p = s_pid[t];
        Ssm[i] = (p >= 0) ? Sglob[(size_t)(p >> SHIFT) * NGRP + g] : 0.f;
    }
    for (int i = tid; i < 128 * NGRP; i += 256) {
        int r = i / NGRP, g = i % NGRP;
        size_t idx = (wrowbase + r) * NGRP + g;
        float s = sc[idx];
        Zsm[i] = zp[idx] - 128.f * s;
        Ssc[i] = s;
    }
    __syncthreads();

    float cT[2][4][4], cG[2][4][4];
    #pragma unroll
    for (int m = 0; m < 2; m++)
        #pragma unroll
        for (int n = 0; n < 4; n++)
            #pragma unroll
            for (int k = 0; k < 4; k++) { cT[m][n][k] = 0.f; cG[m][n][k] = 0.f; }

    // zero-point term: cT[t][r] = sum_g S[t][g] * z'[r][g]
    #pragma unroll 4
    for (int g = 0; g < NGRP; g++) {
        float sv[2][2];
        #pragma unroll
        for (int m = 0; m < 2; m++) {
            int tl = warp_m * 32 + m * 16 + trow;
            sv[m][0] = Ssm[tl * NGRP + g];
            sv[m][1] = Ssm[(tl + 8) * NGRP + g];
        }
        #pragma unroll
        for (int n = 0; n < 4; n++) {
            int rr = warp_n * 32 + n * 8 + tcol;
            float z0 = Zsm[rr * NGRP + g];
            float z1 = Zsm[(rr + 1) * NGRP + g];
            #pragma unroll
            for (int m = 0; m < 2; m++) {
                cT[m][n][0] += sv[m][0] * z0;
                cT[m][n][1] += sv[m][0] * z1;
                cT[m][n][2] += sv[m][1] * z0;
                cT[m][n][3] += sv[m][1] * z1;
            }
        }
    }

    const int lmat = lane >> 3;
    const int lm_off = (((lmat & 1) * 8 + (lane & 7)) * 72 + (lmat >> 1) * 8);

    // ---- main pipelined loop ----
    for (int c = 0; c < NCHUNK; c++) {
        __syncthreads();
        if (c + 1 < NCHUNK)
            prefetch((c + 1) & 1 ? st1 : st0, (c + 1) * 64);
        asm volatile("cp.async.commit_group;");
        asm volatile("cp.async.wait_group 1;");
        __syncthreads();

        char* S = (c & 1) ? st1 : st0;
        const __half*   A = (const __half*)S;
        const uint32_t* W = (const uint32_t*)(S + 9216);

        #pragma unroll
        for (int ks = 0; ks < 4; ks++) {
            const int kb = ks * 16;
            uint32_t bfrag[4][2];
            #pragma unroll
            for (int n = 0; n < 4; n++) {
                int rr = warp_n * 32 + n * 8 + trow;
                uint32_t w0 = W[rr * 8 + ((2 * ks)     ^ trow)];
                uint32_t w1 = W[rr * 8 + ((2 * ks + 1) ^ trow)];
                uint32_t b0 = (w0 >> bsh) & 0xFFu;
                uint32_t b1 = (w1 >> bsh) & 0xFFu;
                // fp16(128+q) = 0x5800 | (q<<3); even col = high nib, odd = low
                bfrag[n][0] = 0x58005800u | ((b0 >> 4) << 3) | ((b0 & 15u) << 19);
                bfrag[n][1] = 0x58005800u | ((b1 >> 4) << 3) | ((b1 & 15u) << 19);
            }
            #pragma unroll
            for (int m = 0; m < 2; m++) {
                uint32_t addr = smaddr(A + (warp_m * 32 + m * 16) * 72 + kb + lm_off);
                uint32_t a0, a1, a2, a3;
                ldsm4(a0, a1, a2, a3, addr);
                #pragma unroll
                for (int n = 0; n < 4; n++)
                    mma_f16(cG[m][n], a0, a1, a2, a3, bfrag[n][0], bfrag[n][1]);
            }
        }

        // group boundary (every 128 k = 2 chunks): fold s_g * P'_g
        if (c & 1) {
            int g = c >> 1;
            #pragma unroll
            for (int n = 0; n < 4; n++) {
                int rr = warp_n * 32 + n * 8 + tcol;
                float s0 = Ssc[rr * NGRP + g];
                float s1 = Ssc[(rr + 1) * NGRP + g];
                #pragma unroll
                for (int m = 0; m < 2; m++) {
                    cT[m][n][0] += s0 * cG[m][n][0];
                    cT[m][n][1] += s1 * cG[m][n][1];
                    cT[m][n][2] += s0 * cG[m][n][2];
                    cT[m][n][3] += s1 * cG[m][n][3];
                    cG[m][n][0] = 0.f; cG[m][n][1] = 0.f;
                    cG[m][n][2] = 0.f; cG[m][n][3] = 0.f;
                }
            }
        }
    }

    // ---- store ----
    #pragma unroll
    for (int m = 0; m < 2; m++) {
        #pragma unroll
        for (int half = 0; half < 2; half++) {
            int tl = warp_m * 32 + m * 16 + trow + half * 8;
            int p = s_pid[tl];
            if (p < 0) continue;
            float cf = PHASE ? g_coef[p] : 1.f;
            float* Crow = C + (size_t)p * RTOT + r0;
            #pragma unroll
            for (int n = 0; n < 4; n++) {
                int rr = warp_n * 32 + n * 8 + tcol;
                float2 v;
                v.x = cT[m][n][half * 2 + 0] * cf;
                v.y = cT[m][n][half * 2 + 1] * cf;
                *(float2*)(Crow + rr) = v;
            }
        }
    }
}

// ---------------------------------------------------------------------------
__global__ void k_comb(float* __restrict__ out) {
    int i = blockIdx.x * blockDim.x + threadIdx.x;
    if (i >= TOK * HID) return;
    int t = i >> 11;
    int c = i & (HID - 1);
    out[i] = g_dn[(size_t)(2 * t) * HID + c] + g_dn[(size_t)(2 * t + 1) * HID + c];
}

// ---------------------------------------------------------------------------
extern "C" void kernel_launch(void* const* d_in, const int* in_sizes, int n_in,
                              void* d_out, int out_size)
{
    (void)out_size;
    int ix = 0, igup = 1, igs_a = 2, igs_b = 3, idnp = 4, ids_a = 5, ids_b = 6,
        irt_a = 7, irt_b = 8;

    int gu_pair[2] = {-1, -1}, dn_pair[2] = {-1, -1}, rt_pair[2] = {-1, -1};
    int f_x = -1, f_gup = -1, f_dnp = -1;
    for (int i = 0; i < n_in; i++) {
        long long s = in_sizes[i];
        if      (s == 2097152LL)  f_x = i;
        else if (s == 67108864LL) f_gup = i;
        else if (s == 33554432LL) f_dnp = i;
        else if (s == 1048576LL)  { if (gu_pair[0] < 0) gu_pair[0] = i; else gu_pair[1] = i; }
        else if (s == 524288LL)   { if (dn_pair[0] < 0) dn_pair[0] = i; else dn_pair[1] = i; }
        else if (s == 2048LL)     { if (rt_pair[0] < 0) rt_pair[0] = i; else rt_pair[1] = i; }
    }
    if (f_x >= 0 && f_gup >= 0 && f_dnp >= 0 &&
        gu_pair[1] >= 0 && dn_pair[1] >= 0 && rt_pair[1] >= 0) {
        ix = f_x; igup = f_gup; idnp = f_dnp;
        igs_a = gu_pair[0]; igs_b = gu_pair[1];
        ids_a = dn_pair[0]; ids_b = dn_pair[1];
        irt_a = rt_pair[0]; irt_b = rt_pair[1];
    }

    const float*   x    = (const float*)  d_in[ix];
    const uint8_t* gu_p = (const uint8_t*)d_in[igup];
    const float*   gu_a = (const float*)  d_in[igs_a];
    const float*   gu_b = (const float*)  d_in[igs_b];
    const uint8_t* dn_p = (const uint8_t*)d_in[idnp];
    const float*   dn_a = (const float*)  d_in[ids_a];
    const float*   dn_b = (const float*)  d_in[ids_b];
    const void*    rt_a = d_in[irt_a];
    const void*    rt_b = d_in[irt_b];
    float*         out  = (float*)        d_out;

    const int SMEM0 = 2 * 13312 + (64 + 128 + 128) * (HID / GSIZE) * 4 + 256;   // ~47.4 KB
    const int SMEM1 = 2 * 13312 + (64 + 128 + 128) * (INTER / GSIZE) * 4 + 256; // ~67.8 KB
    cudaFuncSetAttribute(mma_gemm<0>, cudaFuncAttributeMaxDynamicSharedMemorySize, SMEM0);
    cudaFuncSetAttribute(mma_gemm<1>, cudaFuncAttributeMaxDynamicSharedMemorySize, SMEM1);

    k_detect<<<1, 32>>>((const uint32_t*)gu_p, gu_a, dn_a, (const uint32_t*)rt_a);
    k_zero<<<1, 32>>>();
    k_route<<<NPAIR / 256, 256>>>(rt_a, rt_b);
    k_split<<<TOK * (HID / GSIZE) / 8, 256>>>(x);

    dim3 g0(TWO_I / 128, EXPERTS, NPAIR / 64);   // (64, 8, 32)
    mma_gemm<0><<<g0, 256, SMEM0>>>(gu_p, gu_a, gu_b);

    k_gelu<<<NPAIR * (INTER / GSIZE) / 8, 256>>>();

    dim3 g1(HID / 128, EXPERTS, NPAIR / 64);     // (16, 8, 32)
    mma_gemm<1><<<g1, 256, SMEM1>>>(dn_p, dn_a, dn_b);

    k_comb<<<(TOK * HID) / 256, 256>>>(out);
}